// round 2
// baseline (speedup 1.0000x reference)
#include <cuda_runtime.h>
#include <cuda_bf16.h>

// Problem constants
#define BB   8
#define CC   28
#define HH   256
#define WW   256
#define DG   7
#define CPG  4
#define KH   7
#define NGI  49
#define PADH 3

// smem region sizes (floats)
#define NS_WS1P (NGI*CC*CPG)     // 5488 : stage1 weights [gi][o][c]
#define NS_W2P  (CC*14*8*2)      // 6272 : stage2 weights [o][ip][j(8)][par]
#define MIDW    264              // 3 zero + 256 + 5 zero
#define NS_MID2 (14*MIDW*2)      // 7392 : mid, i-pair interleaved [ip][col][par]
#define NS_SAMP (2*2*WW*2)       // 2048 : double-buffered [buf][cp][w][par]

// ---------------------------------------------------------------------------
__device__ int   d_y0[NGI*HH];
__device__ int   d_y1[NGI*HH];
__device__ float d_wt0[NGI*HH];
__device__ float d_wt1[NGI*HH];
__device__ float d_ws1p[NS_WS1P];
__device__ float d_w2p[NS_W2P];
__device__ float d_B2[CC];

// packed f32x2 FMA: d = a*b + d  (lo/hi lanes independent)
__device__ __forceinline__ void ffma2(unsigned long long& d,
                                      unsigned long long a,
                                      unsigned long long b) {
    asm("fma.rn.f32x2 %0, %1, %2, %0;" : "+l"(d) : "l"(a), "l"(b));
}
__device__ __forceinline__ float lo32(unsigned long long v) {
    return __int_as_float((int)(unsigned int)v);
}
__device__ __forceinline__ float hi32(unsigned long long v) {
    return __int_as_float((int)(v >> 32));
}
// bank-conflict swizzle: toggle bit2 (16B unit) by bit5 of the float offset
__device__ __forceinline__ int swz(int fi) {
    return fi ^ (((fi >> 5) & 1) << 2);
}

// ---------------------------------------------------------------------------
// Setup 1: harmonic sampling tables (yp collapses to (h+1)(i+1)/(g+1)-4).
// ---------------------------------------------------------------------------
__global__ void setup_tables_kernel() {
    int idx = blockIdx.x * blockDim.x + threadIdx.x;
    if (idx >= NGI * HH) return;
    int gi = idx / HH;
    int h  = idx % HH;
    int g  = gi / KH;
    int i  = gi % KH;

    float fh = (float)h, fg = (float)g, fi = (float)i;
    float t   = __fdiv_rn(fh + 1.0f, fg + 1.0f) * (fi + 1.0f);
    float off = -fi + t - (fh + 1.0f);
    float yp  = fh - (float)PADH + fi + off;

    float y0f = floorf(yp);
    float fy  = yp - y0f;
    int   y0i = (int)y0f;

    float v0 = (y0i >= 0 && y0i <= HH - 1) ? 1.0f : 0.0f;
    float v1 = (y0i + 1 >= 0 && y0i + 1 <= HH - 1) ? 1.0f : 0.0f;

    int y0c = y0i < 0 ? 0 : (y0i > HH - 1 ? HH - 1 : y0i);
    int y1i = y0i + 1;
    int y1c = y1i < 0 ? 0 : (y1i > HH - 1 ? HH - 1 : y1i);

    d_y0[idx]  = y0c;
    d_y1[idx]  = y1c;
    d_wt0[idx] = (1.0f - fy) * v0;
    d_wt1[idx] = fy * v1;
}

// ---------------------------------------------------------------------------
// Setup 2: packed weight layouts + conv/group-mix fusion.
//   ws1p[gi][o][c]          = weight[o, g*4+c, i]
//   w2p[o][ip][j][par]      = sum_g w_m[f,g] * w_t[4g+cc, 2ip+par, 0, j]
//   B2[o]                   = sum_g w_m[f,g] * b_t[4g+cc] + b_m[f]
// ---------------------------------------------------------------------------
__global__ void setup_weights_kernel(const float* __restrict__ weight,
                                     const float* __restrict__ w_t,
                                     const float* __restrict__ b_t,
                                     const float* __restrict__ w_m,
                                     const float* __restrict__ b_m) {
    int idx = blockIdx.x * blockDim.x + threadIdx.x;
    if (idx < NS_WS1P) {
        int gi = idx / (CC * CPG);
        int r  = idx % (CC * CPG);
        int o  = r / CPG;
        int c  = r % CPG;
        int g  = gi / KH;
        int i  = gi % KH;
        d_ws1p[idx] = weight[(o * CC + g * CPG + c) * KH + i];
    }
    if (idx < NS_W2P) {
        int o   = idx / 224;          // 14*8*2
        int r   = idx % 224;
        int ip  = r / 16;
        int r2  = r % 16;
        int j   = r2 >> 1;
        int par = r2 & 1;
        float v = 0.0f;
        if (j < 7) {
            int i2 = ip * 2 + par;
            int f  = o / CPG;
            int cc = o % CPG;
            #pragma unroll
            for (int g = 0; g < DG; g++)
                v += w_m[f * DG + g] * w_t[((g * CPG + cc) * CC + i2) * KH + j];
        }
        d_w2p[idx] = v;
    }
    if (idx < CC) {
        int f  = idx / CPG;
        int cc = idx % CPG;
        float s = b_m[idx / CPG];
        #pragma unroll
        for (int g = 0; g < DG; g++)
            s += w_m[f * DG + g] * b_t[g * CPG + cc];
        d_B2[idx] = s;
    }
}

// ---------------------------------------------------------------------------
// Fused main kernel, FFMA2 (f32x2) packed over the reduction-dim parity.
// One block per (b,h) output row; thread = (to: 7 outputs, tw: 4 pixels).
// ---------------------------------------------------------------------------
__global__ void __launch_bounds__(256, 2)
harmonic_fused_kernel(const float* __restrict__ x,
                      const float* __restrict__ bias,
                      float* __restrict__ out) {
    extern __shared__ float sm[];
    float* s_ws1p = sm;                      // 5488
    float* s_w2p  = s_ws1p + NS_WS1P;        // 6272
    float* s_mid2 = s_w2p  + NS_W2P;         // 7392
    float* s_samp = s_mid2 + NS_MID2;        // 2048
    float* s_w0   = s_samp + NS_SAMP;        // 49
    float* s_w1   = s_w0 + NGI;              // 49
    float* s_B2   = s_w1 + NGI;              // 28
    float* s_bias = s_B2 + CC;               // 28
    int*   s_y0   = (int*)(s_bias + CC);     // 49
    int*   s_y1   = s_y0 + NGI;              // 49

    const int tid = threadIdx.x;
    const int h   = blockIdx.x & (HH - 1);
    const int b   = blockIdx.x >> 8;
    const int tw  = tid & 63;
    const int to  = tid >> 6;
    const int w0  = tw << 2;

    // ---- prologue: stage weights & tables ----
    for (int idx = tid; idx < NS_WS1P; idx += 256) s_ws1p[idx] = d_ws1p[idx];
    for (int idx = tid; idx < NS_W2P;  idx += 256) s_w2p[idx]  = d_w2p[idx];
    if (tid < NGI) {
        int t = tid * HH + h;
        s_w0[tid] = d_wt0[t];
        s_w1[tid] = d_wt1[t];
        s_y0[tid] = d_y0[t];
        s_y1[tid] = d_y1[t];
    }
    if (tid < CC) {
        s_B2[tid]   = d_B2[tid];
        s_bias[tid] = bias[tid];
    }
    // zero halo (cols 0..2 and 259..263, both parities, all 14 ip rows)
    if (tid < 224) {
        int ip = tid >> 4, r = tid & 15, par = r & 1, ci = r >> 1;
        int col = ci < 3 ? ci : 256 + ci;
        s_mid2[swz(ip * (MIDW * 2) + col * 2 + par)] = 0.0f;
    }

    const float* xb = x + (size_t)b * CC * HH * WW;

    // precomputed swizzled addresses (buffer 0)
    const int pst0 = swz(tid * 2);            // producer cp0
    const int pst1 = swz(512 + tid * 2);      // producer cp1
    const int cl00 = swz(w0 * 2);             // consumer cp0 pixels 0,1
    const int cl01 = swz(w0 * 2 + 4);         // consumer cp0 pixels 2,3
    const int cl10 = swz(512 + w0 * 2);       // consumer cp1 pixels 0,1
    const int cl11 = swz(512 + w0 * 2 + 4);   // consumer cp1 pixels 2,3

    // ---- pre-sample tap 0 into buffer 0 ----
    {
        int t0 = h;                 // gi=0
        int r0 = d_y0[t0], r1 = d_y1[t0];
        float f0 = d_wt0[t0], f1 = d_wt1[t0];
        float a[4];
        #pragma unroll
        for (int c = 0; c < CPG; c++) {
            float v0 = __ldg(xb + (c * HH + r0) * WW + tid);
            float v1 = __ldg(xb + (c * HH + r1) * WW + tid);
            a[c] = v0 * f0 + v1 * f1;
        }
        *(float2*)(s_samp + pst0) = make_float2(a[0], a[1]);
        *(float2*)(s_samp + pst1) = make_float2(a[2], a[3]);
    }
    __syncthreads();

    unsigned long long acc[7][4];
    #pragma unroll
    for (int k = 0; k < 7; k++)
        #pragma unroll
        for (int m = 0; m < 4; m++) acc[k][m] = 0ULL;

    // ---- stage 1: 49 taps, double-buffered, FFMA2 over (c-even,c-odd) ----
    #pragma unroll 1
    for (int gi = 0; gi < NGI; gi++) {
        const int cur = gi & 1;
        if (gi < NGI - 1) {
            int gn = gi + 1;
            int g  = gn / KH;
            int r0 = s_y0[gn], r1 = s_y1[gn];
            float f0 = s_w0[gn], f1 = s_w1[gn];
            const float* pc = xb + (g * CPG) * (HH * WW);
            float* db = s_samp + (cur ^ 1) * 1024;
            float a[4];
            #pragma unroll
            for (int c = 0; c < CPG; c++) {
                float v0 = __ldg(pc + (c * HH + r0) * WW + tid);
                float v1 = __ldg(pc + (c * HH + r1) * WW + tid);
                a[c] = v0 * f0 + v1 * f1;
            }
            *(float2*)(db + pst0) = make_float2(a[0], a[1]);
            *(float2*)(db + pst1) = make_float2(a[2], a[3]);
        }

        const float* sb = s_samp + cur * 1024;
        ulonglong2 d00 = *(const ulonglong2*)(sb + cl00);
        ulonglong2 d01 = *(const ulonglong2*)(sb + cl01);
        ulonglong2 d10 = *(const ulonglong2*)(sb + cl10);
        ulonglong2 d11 = *(const ulonglong2*)(sb + cl11);

        const float* wb = s_ws1p + (gi * CC + to * 7) * CPG;
        #pragma unroll
        for (int k = 0; k < 7; k++) {
            ulonglong2 wq = *(const ulonglong2*)(wb + k * 4);  // (c0,c1),(c2,c3)
            ffma2(acc[k][0], d00.x, wq.x);
            ffma2(acc[k][1], d00.y, wq.x);
            ffma2(acc[k][2], d01.x, wq.x);
            ffma2(acc[k][3], d01.y, wq.x);
            ffma2(acc[k][0], d10.x, wq.y);
            ffma2(acc[k][1], d10.y, wq.y);
            ffma2(acc[k][2], d11.x, wq.y);
            ffma2(acc[k][3], d11.y, wq.y);
        }
        __syncthreads();
    }

    // ---- write mid (+bias) into i-pair interleaved layout ----
    #pragma unroll
    for (int k = 0; k < 7; k++) {
        int o  = to * 7 + k;
        int ip = o >> 1;
        int par = o & 1;
        float bs = s_bias[o];
        #pragma unroll
        for (int m = 0; m < 4; m++) {
            float v = lo32(acc[k][m]) + hi32(acc[k][m]) + bs;
            s_mid2[swz(ip * (MIDW * 2) + (3 + w0 + m) * 2 + par)] = v;
        }
    }
    __syncthreads();

    // ---- stage 2: fused 1x7 conv + group mix, FFMA2 over (i-even,i-odd) ----
    unsigned long long acc2[7][4];
    #pragma unroll
    for (int k = 0; k < 7; k++)
        #pragma unroll
        for (int m = 0; m < 4; m++) acc2[k][m] = 0ULL;

    const float* w2b = s_w2p + (to * 7) * 224;
    #pragma unroll 1
    for (int ip = 0; ip < 14; ip++) {
        int base = ip * (MIDW * 2) + w0 * 2;    // window cols w0..w0+9 (padded)
        ulonglong2 q0 = *(const ulonglong2*)(s_mid2 + swz(base));
        ulonglong2 q1 = *(const ulonglong2*)(s_mid2 + swz(base + 4));
        ulonglong2 q2 = *(const ulonglong2*)(s_mid2 + swz(base + 8));
        ulonglong2 q3 = *(const ulonglong2*)(s_mid2 + swz(base + 12));
        ulonglong2 q4 = *(const ulonglong2*)(s_mid2 + swz(base + 16));
        unsigned long long m2[10] = {q0.x, q0.y, q1.x, q1.y, q2.x,
                                     q2.y, q3.x, q3.y, q4.x, q4.y};
        #pragma unroll
        for (int k = 0; k < 7; k++) {
            const float* wkb = w2b + k * 224 + ip * 16;
            ulonglong2 wa = *(const ulonglong2*)(wkb);
            ulonglong2 wbq = *(const ulonglong2*)(wkb + 4);
            ulonglong2 wc = *(const ulonglong2*)(wkb + 8);
            ulonglong2 wd = *(const ulonglong2*)(wkb + 12);
            unsigned long long wj[7] = {wa.x, wa.y, wbq.x, wbq.y,
                                        wc.x, wc.y, wd.x};
            #pragma unroll
            for (int j = 0; j < 7; j++)
                #pragma unroll
                for (int m = 0; m < 4; m++)
                    ffma2(acc2[k][m], m2[j + m], wj[j]);
        }
    }

    // ---- store output row ----
    #pragma unroll
    for (int k = 0; k < 7; k++) {
        int o = to * 7 + k;
        float bq = s_B2[o];
        float4 v;
        v.x = lo32(acc2[k][0]) + hi32(acc2[k][0]) + bq;
        v.y = lo32(acc2[k][1]) + hi32(acc2[k][1]) + bq;
        v.z = lo32(acc2[k][2]) + hi32(acc2[k][2]) + bq;
        v.w = lo32(acc2[k][3]) + hi32(acc2[k][3]) + bq;
        *(float4*)(out + ((size_t)(b * CC + o) * HH + h) * WW + w0) = v;
    }
}

// ---------------------------------------------------------------------------
extern "C" void kernel_launch(void* const* d_in, const int* in_sizes, int n_in,
                              void* d_out, int out_size) {
    const float* x      = (const float*)d_in[0];
    const float* weight = (const float*)d_in[1];
    const float* bias   = (const float*)d_in[2];
    const float* w_t    = (const float*)d_in[3];
    const float* b_t    = (const float*)d_in[4];
    const float* w_m    = (const float*)d_in[5];
    const float* b_m    = (const float*)d_in[6];
    float* out = (float*)d_out;

    setup_tables_kernel<<<(NGI * HH + 255) / 256, 256>>>();
    setup_weights_kernel<<<(NS_W2P + 255) / 256, 256>>>(weight, w_t, b_t, w_m, b_m);

    const int smem_bytes =
        (NS_WS1P + NS_W2P + NS_MID2 + NS_SAMP + NGI * 2 + CC * 2 + NGI * 2) * 4;
    cudaFuncSetAttribute(harmonic_fused_kernel,
                         cudaFuncAttributeMaxDynamicSharedMemorySize, smem_bytes);
    harmonic_fused_kernel<<<BB * HH, 256, smem_bytes>>>(x, bias, out);
}